// round 15
// baseline (speedup 1.0000x reference)
#include <cuda_runtime.h>
#include <cstdint>

// Depthwise 9x9 conv, stride 1, pad 4. X:(32,64,256,256) fp32, one shared kernel.
// R14 = R13 (two-column window-sharing chains, image-pair f32x2 packing)
// + COLUMN-UNIT XOR SWIZZLE to kill the 16B-lane-stride bank conflicts:
//   smem 8B-unit column index c8 -> c8 ^ ((c8>>4)&1).
//   - all lanes of a wavefront read the same row, so swizzling the column
//     part only preserves correctness and is computed ONCE per window pass.
//   - colliding lane pair (i, i+8) differs by 16 units -> parity bit flips
//     -> banks separate; conflict-free within each 16-lane wavefront.
//   - staging float4s stay in their 16B slot, halves swapped when
//     (c4>>2)&1 == 1 (pure component permutation, no extra stores).

#define IMG 256
#define IMGSZ (IMG * IMG)
#define SROW 144                           // interleaved floats per smem row
#define SROWU 72                           // 8B units per smem row
#define SROWS 72                           // 64 + 8 halo rows
#define NU4 (SROWS * 18)                   // 1296 four-col staging units
#define SMEM_BYTES (SROWS * SROW * 4)      // 41472

__device__ unsigned long long d_kstage[81];
__constant__ unsigned long long cKpack[81];

__device__ __forceinline__ unsigned long long pack2(float lo, float hi) {
    unsigned long long r;
    asm("mov.b64 %0, {%1, %2};" : "=l"(r) : "f"(lo), "f"(hi));
    return r;
}

__device__ __forceinline__ void ffma2(unsigned long long& d,
                                      unsigned long long a,
                                      unsigned long long b) {
    asm("fma.rn.f32x2 %0, %1, %2, %0;" : "+l"(d) : "l"(a), "l"(b));
}

__global__ void pack_kernel(const float* __restrict__ K) {
    int i = threadIdx.x;
    if (i < 81) {
        float v = K[i];
        d_kstage[i] = pack2(v, v);
    }
}

// One window pass over 24 rows. base points at the (already swizzled) column
// unit in the first row; rows advance by SROW floats.
template <bool DO_A, bool DO_B>
__device__ __forceinline__ void window_pass(
    const float* base, unsigned long long* accA, unsigned long long* accB,
    const unsigned long long* ka, const unsigned long long* kb)
{
    unsigned long long P[3];
    P[0] = *(const unsigned long long*)(base);
    P[1] = *(const unsigned long long*)(base + SROW);
    #pragma unroll
    for (int t = 0; t < 24; ++t) {
        if (t + 2 < 24)
            P[(t + 2) % 3] =
                *(const unsigned long long*)(base + (t + 2) * SROW);
        const unsigned long long Pc = P[t % 3];
        #pragma unroll
        for (int u = 0; u < 9; ++u) {
            const int o = t - u;
            if (o >= 0 && o < 16) {
                if (DO_A) ffma2(accA[o], Pc, ka[u]);
                if (DO_B) ffma2(accB[o], Pc, kb[u]);
            }
        }
    }
}

__global__ __launch_bounds__(128, 4)
void conv9x9_kernel(const float* __restrict__ X,
                    float* __restrict__ out) {
    extern __shared__ float smem[];

    const int bx    = blockIdx.x;
    const int pair  = bx >> 4;             // 1024 image pairs
    const int t16   = bx & 15;             // 4x4 tiles of 64x64
    const int row0  = (t16 >> 2) * 64;
    const int col0  = (t16 & 3) * 64;

    const float* __restrict__ XA = X + (size_t)(2 * pair)     * IMGSZ;
    const float* __restrict__ XB = X + (size_t)(2 * pair + 1) * IMGSZ;
    const int tid = threadIdx.x;

    // ---- Stage interleaved tile with column-swizzle ----
    {
        int r  = tid / 18;
        int c4 = tid - r * 18;
        int idx = tid;
        #pragma unroll 1
        while (idx < NU4) {
            const int gr  = row0 - 4 + r;
            const int gc0 = col0 - 4 + 4 * c4;   // 16B-aligned; fully in or out
            float4 a = make_float4(0.f, 0.f, 0.f, 0.f);
            float4 b = make_float4(0.f, 0.f, 0.f, 0.f);
            if ((unsigned)gr < IMG && (unsigned)gc0 < IMG) {
                a = *(const float4*)&XA[gr * IMG + gc0];
                b = *(const float4*)&XB[gr * IMG + gc0];
            }
            // column units 4c4..4c4+3; swizzle swaps halves within each 16B
            // slot when bit ((4*c4)>>4)&1 = (c4>>2)&1 is set.
            float* dst = &smem[r * SROW + 8 * c4];
            if ((c4 >> 2) & 1) {
                *(float4*)(dst)     = make_float4(a.y, b.y, a.x, b.x);
                *(float4*)(dst + 4) = make_float4(a.w, b.w, a.z, b.z);
            } else {
                *(float4*)(dst)     = make_float4(a.x, b.x, a.y, b.y);
                *(float4*)(dst + 4) = make_float4(a.z, b.z, a.w, b.w);
            }

            idx += 128;                    // 128 = 7*18 + 2
            r  += 7;
            c4 += 2;
            if (c4 >= 18) { c4 -= 18; r += 1; }
        }
    }
    __syncthreads();

    const int cu    = tid & 31;            // colunit: output cols jA, jA+1
    const int rg    = tid >> 5;            // 4 rowgroups x 16 rows
    const int rbase = rg * 16;
    float* rowbase = &smem[rbase * SROW];

    // Window w base: column unit c8 = 2*cu + w, swizzled.
    #define WBASE(w) (rowbase + 2 * ((2 * cu + (w)) ^ (((2 * cu + (w)) >> 4) & 1)))

    unsigned long long accA[16], accB[16];
    #pragma unroll
    for (int i = 0; i < 16; ++i) { accA[i] = 0ull; accB[i] = 0ull; }

    unsigned long long kra[9], krb[9];

    // Section 1: window 0 -> col A, tap v=0.
    #pragma unroll
    for (int u = 0; u < 9; ++u) kra[u] = cKpack[u * 9 + 0];
    window_pass<true, false>(WBASE(0), accA, accB, kra, krb);

    // Section 2: windows w=1..8, unrolled by 2 to rotate coefficient buffers.
    // Window w: col A tap v=w, col B tap v=w-1.
    #pragma unroll 1
    for (int w = 1; w <= 8; w += 2) {
        #pragma unroll
        for (int u = 0; u < 9; ++u) krb[u] = cKpack[u * 9 + w];
        window_pass<true, true>(WBASE(w), accA, accB, krb, kra);
        #pragma unroll
        for (int u = 0; u < 9; ++u) kra[u] = cKpack[u * 9 + w + 1];
        window_pass<true, true>(WBASE(w + 1), accA, accB, kra, krb);
    }

    // Section 3: window 9 -> col B, tap v=8 (in kra after the loop).
    window_pass<false, true>(WBASE(9), accA, accB, krb, kra);
    #undef WBASE

    const int jA = 2 * cu;
    float* __restrict__ OA = out + (size_t)(2 * pair)     * IMGSZ;
    float* __restrict__ OB = out + (size_t)(2 * pair + 1) * IMGSZ;
    #pragma unroll
    for (int o = 0; o < 16; ++o) {
        float aA, bA, aB, bB;   // a/b = image, A/B = column
        asm("mov.b64 {%0, %1}, %2;" : "=f"(aA), "=f"(bA) : "l"(accA[o]));
        asm("mov.b64 {%0, %1}, %2;" : "=f"(aB), "=f"(bB) : "l"(accB[o]));
        const int off = (row0 + rbase + o) * IMG + col0 + jA;
        *(float2*)&OA[off] = make_float2(aA, aB);
        *(float2*)&OB[off] = make_float2(bA, bB);
    }
}

extern "C" void kernel_launch(void* const* d_in, const int* in_sizes, int n_in,
                              void* d_out, int out_size) {
    const float* X = (const float*)d_in[0];
    const float* K = (const float*)d_in[1];
    if (n_in >= 2 && in_sizes[0] == 81) {  // metadata-order safety
        const float* t = X; X = K; K = t;
    }
    pack_kernel<<<1, 128>>>(K);
    void* stage_ptr = nullptr;
    cudaGetSymbolAddress(&stage_ptr, d_kstage);
    cudaMemcpyToSymbolAsync(cKpack, stage_ptr, 81 * sizeof(unsigned long long),
                            0, cudaMemcpyDeviceToDevice, 0);
    cudaFuncSetAttribute(conv9x9_kernel,
                         cudaFuncAttributeMaxDynamicSharedMemorySize,
                         SMEM_BYTES);
    conv9x9_kernel<<<16384, 128, SMEM_BYTES>>>(X, (float*)d_out);
}

// round 16
// speedup vs baseline: 1.0183x; 1.0183x over previous
#include <cuda_runtime.h>
#include <cstdint>

// Depthwise 9x9 conv, stride 1, pad 4. X:(32,64,256,256) fp32, one shared kernel.
// R15 = R14 (two-column window-sharing chains, image-pair f32x2 packing,
// column-unit XOR swizzle) with the 5th CTA enabled:
//   __launch_bounds__(128, 5): regs 90 <= 102 cap, smem 5 x 41.5KB = 207KB
//   <= 228KB -> 20 warps/SM (+25% latency cover).
// R14 showed the swizzle kills conflicts (L1 82.5 -> 51.1%) but 16 warps were
// already absorbing them; at 20 warps the un-swizzled version would saturate
// the crossbar, so the swizzle + extra CTA compound.

#define IMG 256
#define IMGSZ (IMG * IMG)
#define SROW 144                           // interleaved floats per smem row
#define SROWS 72                           // 64 + 8 halo rows
#define NU4 (SROWS * 18)                   // 1296 four-col staging units
#define SMEM_BYTES (SROWS * SROW * 4)      // 41472

__device__ unsigned long long d_kstage[81];
__constant__ unsigned long long cKpack[81];

__device__ __forceinline__ unsigned long long pack2(float lo, float hi) {
    unsigned long long r;
    asm("mov.b64 %0, {%1, %2};" : "=l"(r) : "f"(lo), "f"(hi));
    return r;
}

__device__ __forceinline__ void ffma2(unsigned long long& d,
                                      unsigned long long a,
                                      unsigned long long b) {
    asm("fma.rn.f32x2 %0, %1, %2, %0;" : "+l"(d) : "l"(a), "l"(b));
}

__global__ void pack_kernel(const float* __restrict__ K) {
    int i = threadIdx.x;
    if (i < 81) {
        float v = K[i];
        d_kstage[i] = pack2(v, v);
    }
}

// One window pass over 24 rows. base points at the (already swizzled) column
// unit in the first row; rows advance by SROW floats.
template <bool DO_A, bool DO_B>
__device__ __forceinline__ void window_pass(
    const float* base, unsigned long long* accA, unsigned long long* accB,
    const unsigned long long* ka, const unsigned long long* kb)
{
    unsigned long long P[3];
    P[0] = *(const unsigned long long*)(base);
    P[1] = *(const unsigned long long*)(base + SROW);
    #pragma unroll
    for (int t = 0; t < 24; ++t) {
        if (t + 2 < 24)
            P[(t + 2) % 3] =
                *(const unsigned long long*)(base + (t + 2) * SROW);
        const unsigned long long Pc = P[t % 3];
        #pragma unroll
        for (int u = 0; u < 9; ++u) {
            const int o = t - u;
            if (o >= 0 && o < 16) {
                if (DO_A) ffma2(accA[o], Pc, ka[u]);
                if (DO_B) ffma2(accB[o], Pc, kb[u]);
            }
        }
    }
}

__global__ __launch_bounds__(128, 5)
void conv9x9_kernel(const float* __restrict__ X,
                    float* __restrict__ out) {
    extern __shared__ float smem[];

    const int bx    = blockIdx.x;
    const int pair  = bx >> 4;             // 1024 image pairs
    const int t16   = bx & 15;             // 4x4 tiles of 64x64
    const int row0  = (t16 >> 2) * 64;
    const int col0  = (t16 & 3) * 64;

    const float* __restrict__ XA = X + (size_t)(2 * pair)     * IMGSZ;
    const float* __restrict__ XB = X + (size_t)(2 * pair + 1) * IMGSZ;
    const int tid = threadIdx.x;

    // ---- Stage interleaved tile with column-swizzle ----
    {
        int r  = tid / 18;
        int c4 = tid - r * 18;
        int idx = tid;
        #pragma unroll 1
        while (idx < NU4) {
            const int gr  = row0 - 4 + r;
            const int gc0 = col0 - 4 + 4 * c4;   // 16B-aligned; fully in or out
            float4 a = make_float4(0.f, 0.f, 0.f, 0.f);
            float4 b = make_float4(0.f, 0.f, 0.f, 0.f);
            if ((unsigned)gr < IMG && (unsigned)gc0 < IMG) {
                a = *(const float4*)&XA[gr * IMG + gc0];
                b = *(const float4*)&XB[gr * IMG + gc0];
            }
            // column units 4c4..4c4+3; swizzle swaps halves within each 16B
            // slot when bit ((4*c4)>>4)&1 = (c4>>2)&1 is set.
            float* dst = &smem[r * SROW + 8 * c4];
            if ((c4 >> 2) & 1) {
                *(float4*)(dst)     = make_float4(a.y, b.y, a.x, b.x);
                *(float4*)(dst + 4) = make_float4(a.w, b.w, a.z, b.z);
            } else {
                *(float4*)(dst)     = make_float4(a.x, b.x, a.y, b.y);
                *(float4*)(dst + 4) = make_float4(a.z, b.z, a.w, b.w);
            }

            idx += 128;                    // 128 = 7*18 + 2
            r  += 7;
            c4 += 2;
            if (c4 >= 18) { c4 -= 18; r += 1; }
        }
    }
    __syncthreads();

    const int cu    = tid & 31;            // colunit: output cols jA, jA+1
    const int rg    = tid >> 5;            // 4 rowgroups x 16 rows
    const int rbase = rg * 16;
    float* rowbase = &smem[rbase * SROW];

    // Window w base: column unit c8 = 2*cu + w, swizzled.
    #define WBASE(w) (rowbase + 2 * ((2 * cu + (w)) ^ (((2 * cu + (w)) >> 4) & 1)))

    unsigned long long accA[16], accB[16];
    #pragma unroll
    for (int i = 0; i < 16; ++i) { accA[i] = 0ull; accB[i] = 0ull; }

    unsigned long long kra[9], krb[9];

    // Section 1: window 0 -> col A, tap v=0.
    #pragma unroll
    for (int u = 0; u < 9; ++u) kra[u] = cKpack[u * 9 + 0];
    window_pass<true, false>(WBASE(0), accA, accB, kra, krb);

    // Section 2: windows w=1..8, unrolled by 2 to rotate coefficient buffers.
    // Window w: col A tap v=w, col B tap v=w-1.
    #pragma unroll 1
    for (int w = 1; w <= 8; w += 2) {
        #pragma unroll
        for (int u = 0; u < 9; ++u) krb[u] = cKpack[u * 9 + w];
        window_pass<true, true>(WBASE(w), accA, accB, krb, kra);
        #pragma unroll
        for (int u = 0; u < 9; ++u) kra[u] = cKpack[u * 9 + w + 1];
        window_pass<true, true>(WBASE(w + 1), accA, accB, kra, krb);
    }

    // Section 3: window 9 -> col B, tap v=8 (in kra after the loop).
    window_pass<false, true>(WBASE(9), accA, accB, krb, kra);
    #undef WBASE

    const int jA = 2 * cu;
    float* __restrict__ OA = out + (size_t)(2 * pair)     * IMGSZ;
    float* __restrict__ OB = out + (size_t)(2 * pair + 1) * IMGSZ;
    #pragma unroll
    for (int o = 0; o < 16; ++o) {
        float aA, bA, aB, bB;   // a/b = image, A/B = column
        asm("mov.b64 {%0, %1}, %2;" : "=f"(aA), "=f"(bA) : "l"(accA[o]));
        asm("mov.b64 {%0, %1}, %2;" : "=f"(aB), "=f"(bB) : "l"(accB[o]));
        const int off = (row0 + rbase + o) * IMG + col0 + jA;
        *(float2*)&OA[off] = make_float2(aA, aB);
        *(float2*)&OB[off] = make_float2(bA, bB);
    }
}

extern "C" void kernel_launch(void* const* d_in, const int* in_sizes, int n_in,
                              void* d_out, int out_size) {
    const float* X = (const float*)d_in[0];
    const float* K = (const float*)d_in[1];
    if (n_in >= 2 && in_sizes[0] == 81) {  // metadata-order safety
        const float* t = X; X = K; K = t;
    }
    pack_kernel<<<1, 128>>>(K);
    void* stage_ptr = nullptr;
    cudaGetSymbolAddress(&stage_ptr, d_kstage);
    cudaMemcpyToSymbolAsync(cKpack, stage_ptr, 81 * sizeof(unsigned long long),
                            0, cudaMemcpyDeviceToDevice, 0);
    cudaFuncSetAttribute(conv9x9_kernel,
                         cudaFuncAttributeMaxDynamicSharedMemorySize,
                         SMEM_BYTES);
    conv9x9_kernel<<<16384, 128, SMEM_BYTES>>>(X, (float*)d_out);
}